// round 2
// baseline (speedup 1.0000x reference)
#include <cuda_runtime.h>

// Fused masked-scale MSE, round 2:
//  - int32 indexing, exact-division main loop (no tail predicates on this shape)
//  - __ldcs streaming loads (no L2 reuse to preserve)
//  - single kernel: last-block ticket writes the final mean and resets scratch,
//    so the graph replays deterministically with no zero-init launch.

__device__ float        g_partial = 0.0f;
__device__ unsigned int g_ticket  = 0u;

__device__ __forceinline__ float elem_term(float n, float l) {
    // labels are exactly 0.0f, 1.0f, or 2.0f
    float sn = (l == 1.0f) ? 10.0f : ((l == 2.0f) ? 5.0f : 1.0f);
    float sl = (l == 0.0f) ? 1.0f : 10.0f;
    float d = fmaf(n, sn, -l * sl);
    return fmaf(d, d, 0.0f);
}

__global__ void __launch_bounds__(256)
mse_loss_kernel(const float4* __restrict__ n4,
                const float4* __restrict__ l4,
                float* __restrict__ out,
                int n_vec,        // number of float4 elements
                int per_thread,   // full iterations per thread (exact part)
                float inv_n)
{
    const int nthreads = gridDim.x * blockDim.x;
    int i = blockIdx.x * blockDim.x + threadIdx.x;

    float acc = 0.0f;

    #pragma unroll 4
    for (int k = 0; k < per_thread; k++) {
        float4 a = __ldcs(n4 + i);
        float4 b = __ldcs(l4 + i);
        acc += elem_term(a.x, b.x);
        acc += elem_term(a.y, b.y);
        acc += elem_term(a.z, b.z);
        acc += elem_term(a.w, b.w);
        i += nthreads;
    }
    // tail (not taken for 4096x8192, kept for generality)
    if (i < n_vec) {
        float4 a = __ldcs(n4 + i);
        float4 b = __ldcs(l4 + i);
        acc += elem_term(a.x, b.x);
        acc += elem_term(a.y, b.y);
        acc += elem_term(a.z, b.z);
        acc += elem_term(a.w, b.w);
    }

    // warp reduction
    #pragma unroll
    for (int off = 16; off > 0; off >>= 1)
        acc += __shfl_down_sync(0xffffffffu, acc, off);

    __shared__ float warp_sums[8];
    int lane = threadIdx.x & 31;
    int wid  = threadIdx.x >> 5;
    if (lane == 0) warp_sums[wid] = acc;
    __syncthreads();

    if (wid == 0) {
        float v = (lane < (int)(blockDim.x >> 5)) ? warp_sums[lane] : 0.0f;
        #pragma unroll
        for (int off = 4; off > 0; off >>= 1)
            v += __shfl_down_sync(0xffffffffu, v, off);

        if (lane == 0) {
            atomicAdd(&g_partial, v);
            __threadfence();
            unsigned int ticket = atomicAdd(&g_ticket, 1u);
            if (ticket == gridDim.x - 1) {
                // all block partials are visible; finish and reset for next replay
                out[0] = g_partial * inv_n;
                g_partial = 0.0f;
                g_ticket  = 0u;
            }
        }
    }
}

extern "C" void kernel_launch(void* const* d_in, const int* in_sizes, int n_in,
                              void* d_out, int out_size)
{
    const float4* norms  = (const float4*)d_in[0];
    const float4* labels = (const float4*)d_in[1];
    float* out = (float*)d_out;

    int n_elems = in_sizes[0];          // 33554432
    int n_vec   = n_elems / 4;          // 8388608
    float inv_n = 1.0f / (float)n_elems;

    const int threads = 256;
    const int blocks  = 2048;           // 524288 threads -> 16 float4/thread exact
    int total = threads * blocks;
    int per_thread = n_vec / total;     // 16 on this shape

    mse_loss_kernel<<<blocks, threads>>>(norms, labels, out,
                                         n_vec, per_thread, inv_n);
}